// round 17
// baseline (speedup 1.0000x reference)
#include <cuda_runtime.h>

#define BB   512
#define SS   17
#define LL   81
#define VV   13030
#define ENCD 240
#define OED  80
#define PED  60
#define IND  380     // ENC + OE + PE
#define HD   200
#define G4H  800     // 4*H
#define KPAD 592     // 37*16, padded K for gates GEMM (reordered [h|enc|oe|pe|0])

// ---------------- scratch (static device globals; no allocation) ----------------
__device__ __align__(16) unsigned g_gW_hi[G4H * KPAD];   // permuted+packed gate weights
__device__ __align__(16) unsigned g_gW_lo[G4H * KPAD];
__device__ __align__(16) float    g_gbias[G4H];
__device__ __align__(16) unsigned g_oW_hi[VV * HD];
__device__ __align__(16) unsigned g_oW_lo[VV * HD];
__device__ __align__(16) unsigned g_le_hi[SS * BB * ENCD];
__device__ __align__(16) unsigned g_le_lo[SS * BB * ENCD];
__device__ __align__(16) unsigned g_pe_hi[BB * PED];
__device__ __align__(16) unsigned g_pe_lo[BB * PED];
__device__ __align__(16) unsigned g_h_hi[BB * HD];
__device__ __align__(16) unsigned g_h_lo[BB * HD];
__device__ __align__(16) unsigned g_oe_hi[BB * OED];
__device__ __align__(16) unsigned g_oe_lo[BB * OED];
__device__ __align__(16) float    g_c[BB * HD];
__device__ int      g_invalid[BB];
__device__ unsigned g_keys[2 * SS];
__device__ unsigned long long g_amax[BB];
__device__ int      g_done[8];                           // per-b-stripe fan-in counters
__device__ __align__(16) float g_scores[BB * VV];        // scratch when no scores output

// ---------------- threefry2x32 (matches jax/_src/prng.py reference) ----------------
__device__ __forceinline__ uint2 tf2x32(unsigned k0, unsigned k1,
                                        unsigned x0, unsigned x1) {
    unsigned ks2 = k0 ^ k1 ^ 0x1BD11BDAu;
    x0 += k0; x1 += k1;
#define TFR(r) { x0 += x1; x1 = __funnelshift_l(x1, x1, (r)); x1 ^= x0; }
    TFR(13) TFR(15) TFR(26) TFR(6)
    x0 += k1; x1 += ks2 + 1u;
    TFR(17) TFR(29) TFR(16) TFR(24)
    x0 += ks2; x1 += k0 + 2u;
    TFR(13) TFR(15) TFR(26) TFR(6)
    x0 += k0; x1 += k1 + 3u;
    TFR(17) TFR(29) TFR(16) TFR(24)
    x0 += k1; x1 += ks2 + 4u;
    TFR(13) TFR(15) TFR(26) TFR(6)
    x0 += ks2; x1 += k0 + 5u;
#undef TFR
    return make_uint2(x0, x1);
}

// ---------------- accurate fp32 natural log (fdlibm e_logf; fast-math-proof) ----------------
__device__ __forceinline__ float alogf(float x) {
    int ib = __float_as_int(x);
    int k  = ((ib >> 23) & 0xFF) - 126;
    float m = __int_as_float((ib & 0x007FFFFF) | 0x3F000000);
    if (m < 0.70710678f) { m = m + m; k -= 1; }
    float f = m - 1.0f;
    float s = f / (2.0f + f);
    float z = s * s;
    float w = z * z;
    float t1 = w * (0.40000972152f + w * 0.24279078841f);
    float t2 = z * (0.66666662693f + w * 0.28498786688f);
    float R  = t2 + t1;
    float hfsq = 0.5f * f * f;
    float dk = (float)k;
    return dk * 0.69313812256f - ((hfsq - (s * (hfsq + R) + dk * 9.0580006145e-06f)) - f);
}

// ---------------- tf32 helpers ----------------
__device__ __forceinline__ unsigned f2tf32(float x) {
    unsigned r;
    asm("cvt.rna.tf32.f32 %0, %1;" : "=r"(r) : "f"(x));
    return r;
}
__device__ __forceinline__ void mma_tf32(float* c, const unsigned* a, const unsigned* b) {
    asm volatile(
        "mma.sync.aligned.m16n8k8.row.col.f32.tf32.tf32.f32 "
        "{%0,%1,%2,%3}, {%4,%5,%6,%7}, {%8,%9}, {%0,%1,%2,%3};\n"
        : "+f"(c[0]), "+f"(c[1]), "+f"(c[2]), "+f"(c[3])
        : "r"(a[0]), "r"(a[1]), "r"(a[2]), "r"(a[3]), "r"(b[0]), "r"(b[1]));
}
__device__ __forceinline__ void split1(float x, unsigned& hi, unsigned& lo) {
    hi = f2tf32(x);
    lo = f2tf32(x - __uint_as_float(hi));
}

// cp.async 16B with zero-fill predicate
__device__ __forceinline__ void cpa16(void* sdst, const void* gsrc, bool pred) {
    unsigned saddr = (unsigned)__cvta_generic_to_shared(sdst);
    int sz = pred ? 16 : 0;
    asm volatile("cp.async.cg.shared.global [%0], [%1], 16, %2;\n"
                 :: "r"(saddr), "l"(gsrc), "r"(sz));
}

// ---------------- gumbel candidate processing (identical math to prior rounds) ----------------
__device__ __forceinline__ float gproc(float sm, int vv, int b,
                                       unsigned k1t, unsigned k2t,
                                       float rb, unsigned long long& best) {
    uint2 r = tf2x32(k1t, k2t, 0u, (unsigned)(b * VV + vv));
    unsigned bits = r.x ^ r.y;
    float uf = __uint_as_float((bits >> 9) | 0x3F800000u) - 1.0f;
    uf = fmaxf(uf + 1.17549435e-38f, 1.17549435e-38f);
    float lnu_lo = fmaf((float)__float_as_int(uf), 8.2629582e-8f, -88.029694f);
    float e_min = -lnu_lo - 0.0605f;
    float gub = 3.0e38f;
    if (e_min > 1.17549435e-38f) {
        float lne_lo = fmaf((float)__float_as_int(e_min), 8.2629582e-8f, -88.029694f);
        gub = -lne_lo + 1.0e-3f;
    }
    if (sm + gub < rb) return -3.0e38f;
    float gum = -alogf(-alogf(uf));
    float cv = sm + gum;
    unsigned ub = __float_as_uint(cv);
    ub = (ub & 0x80000000u) ? ~ub : (ub | 0x80000000u);
    unsigned long long packed = ((unsigned long long)ub << 32) | (unsigned)(~(unsigned)vv);
    if (packed > best) best = packed;
    return cv;
}

// unpack the cv float from a packed g_amax value (inverse of the order-preserving map)
__device__ __forceinline__ float unpack_cv(unsigned long long p) {
    if (p == 0ULL) return -3.0e38f;
    unsigned ub = (unsigned)(p >> 32);
    unsigned u = (ub & 0x80000000u) ? (ub & 0x7FFFFFFFu) : ~ub;
    return __uint_as_float(u);
}

// ---------------- pack kernels (run once per launch) ----------------
__global__ __launch_bounds__(256) void pack_gw_kernel(
    const float* __restrict__ W_ih, const float* __restrict__ W_hh,
    const float* __restrict__ b_ih, const float* __restrict__ b_hh) {
    int idx = blockIdx.x * blockDim.x + threadIdx.x;
    if (idx >= G4H * KPAD) return;
    int up = idx / KPAD, k = idx - up * KPAD;
    int orig = (up & 3) * HD + (up >> 2);
    float v = 0.f;
    if (k < HD)        v = W_hh[orig * HD + k];
    else if (k < 580)  v = W_ih[orig * IND + (k - HD)];
    unsigned hi, lo; split1(v, hi, lo);
    g_gW_hi[idx] = hi; g_gW_lo[idx] = lo;
    if (k == 0) g_gbias[up] = b_ih[orig] + b_hh[orig];
}

__global__ __launch_bounds__(256) void pack_ow_kernel(const float* __restrict__ out_W) {
    int idx = blockIdx.x * blockDim.x + threadIdx.x;
    if (idx >= VV * HD) return;
    unsigned hi, lo; split1(out_W[idx], hi, lo);
    g_oW_hi[idx] = hi; g_oW_lo[idx] = lo;
}

// ---------------- kernel A: precompute loc_enc(split)/power_emb(split)/state/keys ----------------
__global__ __launch_bounds__(256) void precompute_kernel(
    const float* __restrict__ enc, const int* __restrict__ loc_idxs,
    const float* __restrict__ power_1h, const float* __restrict__ power_W,
    const float* __restrict__ power_b, const float* __restrict__ master) {
    __shared__ float sM[LL * LL];
    __shared__ float sAl[SS][LL];
    __shared__ float sDen[SS];
    __shared__ int   sLoc[LL];
    int b = blockIdx.x;
    int tid = threadIdx.x;

    for (int i = tid; i < LL * LL; i += 256) sM[i] = master[i];
    if (tid < LL) sLoc[tid] = loc_idxs[b * LL + tid];
    for (int i = tid; i < HD; i += 256) {
        g_h_hi[b * HD + i] = 0u; g_h_lo[b * HD + i] = 0u; g_c[b * HD + i] = 0.f;
    }
    for (int i = tid; i < OED; i += 256) { g_oe_hi[b * OED + i] = 0u; g_oe_lo[b * OED + i] = 0u; }
    if (tid == 0) g_amax[b] = 0ULL;
    if (b == 0 && tid < 8) g_done[tid] = 0;
    if (tid < PED) {
        float acc = power_b[tid];
        for (int j = 0; j < 7; ++j) acc += power_1h[b * 7 + j] * power_W[tid * 7 + j];
        unsigned hi, lo; split1(acc, hi, lo);
        g_pe_hi[b * PED + tid] = hi; g_pe_lo[b * PED + tid] = lo;
    }
    if (b == 0 && tid < SS) {
        uint2 r = tf2x32(0u, 42u, 0u, (unsigned)tid);
        g_keys[2 * tid]     = r.x;
        g_keys[2 * tid + 1] = r.y;
    }
    __syncthreads();

    if (tid == 0) {
        int any = 0;
        for (int l = 0; l < LL; ++l) any |= (sLoc[l] != -1);
        g_invalid[b] = !any;
    }
    for (int e = tid; e < SS * LL; e += 256) {
        int t = e / LL, j = e % LL;
        float a = 0.f;
        for (int l = 0; l < LL; ++l) {
            int li = sLoc[l];
            if (li == t || li == -2) a += sM[l * LL + j];
        }
        sAl[t][j] = a;
    }
    __syncthreads();
    if (tid < SS) {
        float d = 0.f;
        for (int j = 0; j < LL; ++j) d += sAl[tid][j];
        sDen[tid] = d;
    }
    __syncthreads();
    for (int e = tid; e < SS * LL; e += 256) {
        int t = e / LL, j = e % LL;
        float d = sDen[t];
        sAl[t][j] = (d != 0.f) ? sAl[t][j] / d : 0.f;
    }
    __syncthreads();
    if (tid < ENCD) {
        float acc[SS];
#pragma unroll
        for (int t = 0; t < SS; ++t) acc[t] = 0.f;
        for (int l = 0; l < LL; ++l) {
            float v = enc[((size_t)b * LL + l) * ENCD + tid];
#pragma unroll
            for (int t = 0; t < SS; ++t) acc[t] += sAl[t][l] * v;
        }
#pragma unroll
        for (int t = 0; t < SS; ++t) {
            unsigned hi, lo; split1(acc[t], hi, lo);
            size_t o = ((size_t)t * BB + b) * ENCD + tid;
            g_le_hi[o] = hi; g_le_lo[o] = lo;
        }
    }
}

// ---------------- G1: fused gates GEMM + LSTM update (64x64 tiles, 3-stage cp.async pipeline) ----------------
struct GatesSM {
    union {
        struct {
            unsigned AH[3][64][20];
            unsigned AL[3][64][20];
            unsigned BH[3][64][20];
            unsigned BL[3][64][20];
        } p;
        float C[64][68];
    };
};

__global__ __launch_bounds__(256) void gates_fused_kernel(int t) {
    __shared__ GatesSM u;
    __shared__ float sBias[64];
    int tid = threadIdx.x;
    int u0 = blockIdx.x * 64, b0 = blockIdx.y * 64;
    int lane = tid & 31, warp = tid >> 5;
    int wv = warp & 1, wb = warp >> 1;         // 2 (rows) x 4 (cols)
    int g = lane >> 2, tig = lane & 3;

    if (tid < 64) {
        int up = u0 + tid;
        sBias[tid] = (up < G4H) ? g_gbias[up] : 0.f;
    }

    float acc[2][2][4];
#pragma unroll
    for (int mt = 0; mt < 2; ++mt)
#pragma unroll
        for (int nt = 0; nt < 2; ++nt)
#pragma unroll
            for (int q = 0; q < 4; ++q) acc[mt][nt][q] = 0.f;

    int arow = tid >> 2, akp = (tid & 3) * 4;
    int brow = arow,    bkp = akp;
    int up = u0 + arow;
    bool pA = (up < G4H);
    size_t abase = (size_t)(pA ? up : 0) * KPAD;
    int bb = b0 + brow;
    const size_t le_row = (size_t)t * BB * ENCD + (size_t)bb * ENCD;

    const int NIT = KPAD / 16;                 // 37
    auto issue = [&](int it, int bi) {
        int k0 = it * 16;
        cpa16(&u.p.AH[bi][arow][akp], g_gW_hi + abase + k0 + akp, pA);
        cpa16(&u.p.AL[bi][arow][akp], g_gW_lo + abase + k0 + akp, pA);
        int k = k0 + bkp;
        const unsigned *sh = g_h_hi, *sl = g_h_lo;
        bool pB = true;
        if (k < HD)                   { sh = g_h_hi + bb * HD + k;            sl = g_h_lo + bb * HD + k; }
        else if (k < HD + ENCD)       { sh = g_le_hi + le_row + (k - HD);     sl = g_le_lo + le_row + (k - HD); }
        else if (k < HD + ENCD + OED) { sh = g_oe_hi + bb * OED + (k - 440);  sl = g_oe_lo + bb * OED + (k - 440); }
        else if (k < 580)             { sh = g_pe_hi + bb * PED + (k - 520);  sl = g_pe_lo + bb * PED + (k - 520); }
        else                          { pB = false; }
        cpa16(&u.p.BH[bi][brow][bkp], sh, pB);
        cpa16(&u.p.BL[bi][brow][bkp], sl, pB);
    };

    issue(0, 0);
    asm volatile("cp.async.commit_group;");
    issue(1, 1);
    asm volatile("cp.async.commit_group;");
    for (int it = 0; it < NIT; ++it) {
        if (it + 2 < NIT) {
            issue(it + 2, (it + 2) % 3);
            asm volatile("cp.async.commit_group;");
            asm volatile("cp.async.wait_group 2;");
        } else {
            asm volatile("cp.async.wait_group 0;");
        }
        __syncthreads();
        int bi = it % 3;
#pragma unroll
        for (int kk = 0; kk < 16; kk += 8) {
            unsigned afh[2][4], afl[2][4], bfh[2][2], bfl[2][2];
#pragma unroll
            for (int mt = 0; mt < 2; ++mt) {
                int r = wv * 32 + mt * 16 + g;
                afh[mt][0] = u.p.AH[bi][r][kk + tig];
                afh[mt][1] = u.p.AH[bi][r + 8][kk + tig];
                afh[mt][2] = u.p.AH[bi][r][kk + tig + 4];
                afh[mt][3] = u.p.AH[bi][r + 8][kk + tig + 4];
                afl[mt][0] = u.p.AL[bi][r][kk + tig];
                afl[mt][1] = u.p.AL[bi][r + 8][kk + tig];
                afl[mt][2] = u.p.AL[bi][r][kk + tig + 4];
                afl[mt][3] = u.p.AL[bi][r + 8][kk + tig + 4];
            }
#pragma unroll
            for (int nt = 0; nt < 2; ++nt) {
                int c = wb * 16 + nt * 8 + g;
                bfh[nt][0] = u.p.BH[bi][c][kk + tig];
                bfh[nt][1] = u.p.BH[bi][c][kk + tig + 4];
                bfl[nt][0] = u.p.BL[bi][c][kk + tig];
                bfl[nt][1] = u.p.BL[bi][c][kk + tig + 4];
            }
#pragma unroll
            for (int mt = 0; mt < 2; ++mt)
#pragma unroll
                for (int nt = 0; nt < 2; ++nt) {
                    mma_tf32(acc[mt][nt], afh[mt], bfl[nt]);
                    mma_tf32(acc[mt][nt], afl[mt], bfh[nt]);
                    mma_tf32(acc[mt][nt], afh[mt], bfh[nt]);
                }
        }
        __syncthreads();
    }

    // transpose accumulators into C[b][u'-local]
#pragma unroll
    for (int nt = 0; nt < 2; ++nt)
#pragma unroll
        for (int cc = 0; cc < 2; ++cc) {
            int bl = wb * 16 + nt * 8 + 2 * tig + cc;
#pragma unroll
            for (int mt = 0; mt < 2; ++mt)
#pragma unroll
                for (int rr = 0; rr < 2; ++rr) {
                    int vl = wv * 32 + mt * 16 + g + rr * 8;
                    u.C[bl][vl] = acc[mt][nt][rr * 2 + cc];
                }
        }
    __syncthreads();

    // fused LSTM pointwise update
    int base = u0 >> 2;
    int nU = (G4H - u0 >= 64) ? 16 : ((G4H - u0) >> 2);
    int total = 64 * nU;
    for (int e = tid; e < total; e += 256) {
        int bl, un;
        if (nU == 16) { bl = e >> 4; un = e & 15; }
        else          { bl = e / nU; un = e - bl * nU; }
        float gi = u.C[bl][un * 4 + 0] + sBias[un * 4 + 0];
        float gf = u.C[bl][un * 4 + 1] + sBias[un * 4 + 1];
        float gg = u.C[bl][un * 4 + 2] + sBias[un * 4 + 2];
        float go = u.C[bl][un * 4 + 3] + sBias[un * 4 + 3];
        int b = b0 + bl, unit = base + un;
        float cprev = g_c[b * HD + unit];
        float si = 1.f / (1.f + expf(-gi));
        float sf = 1.f / (1.f + expf(-gf));
        float so = 1.f / (1.f + expf(-go));
        float c = sf * cprev + si * tanhf(gg);
        float h = so * tanhf(c);
        g_c[b * HD + unit] = c;
        unsigned hh, hl; split1(h, hh, hl);
        g_h_hi[b * HD + unit] = hh;
        g_h_lo[b * HD + unit] = hl;
    }
}

// ---------------- G3: scores GEMM + fused gumbel-argmax + fan-in finish ----------------
struct ScoresSM {
    unsigned AH[2][128][20];   // 20480 B
    unsigned AL[2][128][20];
    unsigned BH[2][64][20];    // 10240 B
    unsigned BL[2][64][20];
};  // 61440 bytes

// layout: [0,61440) ScoresSM / C alias; [61440,61952) sOutB(128 f);
// [61952,64000) qv (8 warps x 128 u16); [64000,68096) qs (8 x 128 f)
#define SCORES_SMEM 68096

__global__ __launch_bounds__(256) void scores_mma_kernel(
    const float* __restrict__ out_b, const unsigned* __restrict__ order_masks,
    float* __restrict__ sc_base, long long pitch, long long off,
    const float* __restrict__ order_embedding, float* __restrict__ idx_out, int t) {
    extern __shared__ __align__(16) unsigned char dsm[];
    ScoresSM* sm = (ScoresSM*)dsm;
    float (*C)[132] = (float(*)[132])dsm;               // aliases buffers after k-loop
    float* sOutB = (float*)(dsm + 61440);
    unsigned short* qv = (unsigned short*)(dsm + 61952);
    float* qs = (float*)(dsm + 64000);
    __shared__ int sIdx[64];
    __shared__ int sLast;
    int tid = threadIdx.x;
    int v0 = blockIdx.x * 128, b0 = blockIdx.y * 64;
    int lane = tid & 31, warp = tid >> 5;
    int wv = warp & 3, wb = warp >> 2;                  // 4 v-quarters x 2 b-halves
    int g = lane >> 2, tig = lane & 3;

    if (tid < 128) {
        int v = v0 + tid;
        sOutB[tid] = (v < VV) ? out_b[v] : 0.f;
    }

    float acc[2][4][4];
#pragma unroll
    for (int mt = 0; mt < 2; ++mt)
#pragma unroll
        for (int nt = 0; nt < 4; ++nt)
#pragma unroll
            for (int q = 0; q < 4; ++q) acc[mt][nt][q] = 0.f;

    int arow = tid >> 1, akq = (tid & 1) * 8;
    int brow = tid >> 2, bkq = (tid & 3) * 4;
    int va = v0 + arow;
    size_t aoff = (va < VV) ? (size_t)va * HD : 0;
    int bb = b0 + brow;

    const int NIT = 13;
    auto issue = [&](int it, int bi) {
        int k0 = it * 16;
        int kA0 = k0 + akq, kA1 = k0 + akq + 4, kB = k0 + bkq;
        bool pA0 = (va < VV) && (kA0 < HD);
        bool pA1 = (va < VV) && (kA1 < HD);
        bool pB  = (kB < HD);
        int cA0 = pA0 ? kA0 : 0, cA1 = pA1 ? kA1 : 0, cB = pB ? kB : 0;
        cpa16(&sm->AH[bi][arow][akq],     g_oW_hi + aoff + cA0, pA0);
        cpa16(&sm->AH[bi][arow][akq + 4], g_oW_hi + aoff + cA1, pA1);
        cpa16(&sm->AL[bi][arow][akq],     g_oW_lo + aoff + cA0, pA0);
        cpa16(&sm->AL[bi][arow][akq + 4], g_oW_lo + aoff + cA1, pA1);
        cpa16(&sm->BH[bi][brow][bkq],     g_h_hi + bb * HD + cB, pB);
        cpa16(&sm->BL[bi][brow][bkq],     g_h_lo + bb * HD + cB, pB);
    };

    issue(0, 0);
    asm volatile("cp.async.commit_group;");
    for (int it = 0; it < NIT; ++it) {
        if (it + 1 < NIT) issue(it + 1, (it + 1) & 1);
        asm volatile("cp.async.commit_group;");
        asm volatile("cp.async.wait_group 1;");
        __syncthreads();
        int bi = it & 1;
#pragma unroll
        for (int kk = 0; kk < 16; kk += 8) {
            unsigned afh[2][4], afl[2][4], bfh[4][2], bfl[4][2];
#pragma unroll
            for (int mt = 0; mt < 2; ++mt) {
                int r = wv * 32 + mt * 16 + g;
                afh[mt][0] = sm->AH[bi][r][kk + tig];
                afh[mt][1] = sm->AH[bi][r + 8][kk + tig];
                afh[mt][2] = sm->AH[bi][r][kk + tig + 4];
                afh[mt][3] = sm->AH[bi][r + 8][kk + tig + 4];
                afl[mt][0] = sm->AL[bi][r][kk + tig];
                afl[mt][1] = sm->AL[bi][r + 8][kk + tig];
                afl[mt][2] = sm->AL[bi][r][kk + tig + 4];
                afl[mt][3] = sm->AL[bi][r + 8][kk + tig + 4];
            }
#pragma unroll
            for (int nt = 0; nt < 4; ++nt) {
                int c = wb * 32 + nt * 8 + g;
                bfh[nt][0] = sm->BH[bi][c][kk + tig];
                bfh[nt][1] = sm->BH[bi][c][kk + tig + 4];
                bfl[nt][0] = sm->BL[bi][c][kk + tig];
                bfl[nt][1] = sm->BL[bi][c][kk + tig + 4];
            }
#pragma unroll
            for (int mt = 0; mt < 2; ++mt)
#pragma unroll
                for (int nt = 0; nt < 4; ++nt) {
                    mma_tf32(acc[mt][nt], afh[mt], bfl[nt]);
                    mma_tf32(acc[mt][nt], afl[mt], bfh[nt]);
                    mma_tf32(acc[mt][nt], afh[mt], bfh[nt]);
                }
        }
        __syncthreads();
    }

    // transpose accumulators through smem (aliases the now-idle buffers)
#pragma unroll
    for (int nt = 0; nt < 4; ++nt)
#pragma unroll
        for (int cc = 0; cc < 2; ++cc) {
            int bl = wb * 32 + nt * 8 + 2 * tig + cc;
#pragma unroll
            for (int mt = 0; mt < 2; ++mt)
#pragma unroll
                for (int rr = 0; rr < 2; ++rr) {
                    int vl = wv * 32 + mt * 16 + g + rr * 8;
                    C[bl][vl] = acc[mt][nt][rr * 2 + cc];
                }
        }
    __syncthreads();

    // coalesced float2 store with bias + mask; masked value written back to C for the scan
    for (int e = tid; e < 64 * 64; e += 256) {
        int bl = e >> 6, v2 = e & 63;
        int b = b0 + bl;
        int v = v0 + v2 * 2;
        if (v >= VV) continue;
        float2 c = *(float2*)&C[bl][v2 * 2];
        c.x += sOutB[v2 * 2];
        c.y += sOutB[v2 * 2 + 1];
        int inv = g_invalid[b];
        uint2 m2 = *(const uint2*)(order_masks + ((size_t)b * SS + t) * VV + v);
        bool ma = inv || (m2.x != 0u);
        bool mb = inv || (m2.y != 0u);
        float2 r;
        r.x = fminf(c.x, ma ? 9.0e8f : -1.0e8f);
        r.y = fminf(c.y, mb ? 9.0e8f : -1.0e8f);
        *(float2*)&C[bl][v2 * 2] = r;
        *(float2*)(sc_base + (long long)b * pitch + off + v) = r;
    }
    __syncthreads();

    // fused gumbel-argmax scan: warp w owns rows [8w, 8w+8)
    unsigned k1t = g_keys[2 * t], k2t = g_keys[2 * t + 1];
    unsigned short* myqv = qv + warp * 128;
    float* myqs = qs + warp * 128;
#pragma unroll 1
    for (int r8 = 0; r8 < 8; ++r8) {
        int bl = warp * 8 + r8;
        int b = b0 + bl;
        // cross-block pruning seed: any snapshot of g_amax[b] is <= final max (conservative)
        float rb = unpack_cv(g_amax[b]);
        // compact candidates of this row into the warp queue
        int qt = 0;
#pragma unroll
        for (int cch = 0; cch < 4; ++cch) {
            int vl = cch * 32 + lane;
            float sv = C[bl][vl];
            bool cand = (v0 + vl < VV) && (sv != -1.0e8f);
            unsigned mk = __ballot_sync(0xffffffffu, cand);
            int rank = __popc(mk & ((1u << lane) - 1u));
            if (cand) {
                myqv[qt + rank] = (unsigned short)vl;
                myqs[qt + rank] = sv;
            }
            qt += __popc(mk);
        }
        __syncwarp();
        // process queue in waves; rb updated with exact wave max (conservative filter)
        unsigned long long best = 0ULL;
        for (int base = 0; base < qt; base += 32) {
            int i = base + lane;
            float cv = -3.0e38f;
            if (i < qt) {
                int vvg = v0 + (int)myqv[i];
                float smv = myqs[i];
                cv = gproc(smv, vvg, b, k1t, k2t, rb, best);
            }
#pragma unroll
            for (int o = 16; o; o >>= 1)
                cv = fmaxf(cv, __shfl_xor_sync(0xffffffffu, cv, o));
            rb = fmaxf(rb, cv);
        }
#pragma unroll
        for (int o = 16; o; o >>= 1) {
            unsigned long long ob = __shfl_xor_sync(0xffffffffu, best, o);
            if (ob > best) best = ob;
        }
        if (lane == 0 && best) atomicMax(&g_amax[b], best);
        __syncwarp();
    }

    // ---- fan-in finish: last block of this b-stripe finalizes the sample ----
    __syncthreads();
    if (tid == 0) {
        __threadfence();
        int ret = atomicAdd(&g_done[blockIdx.y], 1);
        sLast = (ret == (int)gridDim.x - 1);
    }
    __syncthreads();
    if (sLast) {
        __threadfence();
        if (tid < 64) {
            int b = b0 + tid;
            unsigned long long p = g_amax[b];
            int idx = (p == 0ULL) ? 0 : (int)(~(unsigned)(p & 0xFFFFFFFFu));
            if (idx < 0) idx = 0;
            if (idx >= VV) idx = VV - 1;
            sIdx[tid] = idx;
            g_amax[b] = 0ULL;
            if (idx_out) idx_out[b * SS + t] = (float)idx;
            if (tid == 0) g_done[blockIdx.y] = 0;
        }
        __syncthreads();
        for (int e = tid; e < 64 * OED; e += 256) {
            int bl = e / OED, d = e - bl * OED;
            int b = b0 + bl;
            float val = order_embedding[(size_t)sIdx[bl] * OED + d];
            unsigned hh, hl; split1(val, hh, hl);
            g_oe_hi[b * OED + d] = hh;
            g_oe_lo[b * OED + d] = hl;
        }
    }
}

// ---------------- launch ----------------
extern "C" void kernel_launch(void* const* d_in, const int* in_sizes, int n_in,
                              void* d_out, int out_size) {
    const float*    enc        = (const float*)d_in[0];
    const int*      loc_idxs   = (const int*)d_in[2];
    const unsigned* ord_masks  = (const unsigned*)d_in[3];
    const float*    power_1h   = (const float*)d_in[4];
    const float*    order_emb  = (const float*)d_in[5];
    const float*    power_W    = (const float*)d_in[6];
    const float*    power_b    = (const float*)d_in[7];
    const float*    W_ih       = (const float*)d_in[8];
    const float*    W_hh       = (const float*)d_in[9];
    const float*    b_ih       = (const float*)d_in[10];
    const float*    b_hh       = (const float*)d_in[11];
    const float*    out_W      = (const float*)d_in[12];
    const float*    out_b      = (const float*)d_in[13];
    const float*    master     = (const float*)d_in[14];

    float* out = (float*)d_out;
    float* idx_out = nullptr;
    float* scores_out = nullptr;
    const long long NSC = (long long)BB * SS * VV;
    if ((long long)out_size == NSC + (long long)BB * SS) { idx_out = out; scores_out = out + BB * SS; }
    else if ((long long)out_size == NSC)                 { scores_out = out; }
    else if (out_size == BB * SS)                        { idx_out = out; }
    else { scores_out = out; }

    float* g_scores_ptr = nullptr;
    cudaGetSymbolAddress((void**)&g_scores_ptr, g_scores);
    float*    sc_base = scores_out ? scores_out : g_scores_ptr;
    long long pitch   = scores_out ? (long long)SS * VV : (long long)VV;

    cudaFuncSetAttribute(scores_mma_kernel,
                         cudaFuncAttributeMaxDynamicSharedMemorySize, SCORES_SMEM);

    precompute_kernel<<<BB, 256>>>(enc, loc_idxs, power_1h, power_W, power_b, master);
    pack_gw_kernel<<<(G4H * KPAD + 255) / 256, 256>>>(W_ih, W_hh, b_ih, b_hh);
    pack_ow_kernel<<<(VV * HD + 255) / 256, 256>>>(out_W);

    dim3 g1grid((G4H + 63) / 64, BB / 64);           // 13 x 8 = 104 blocks
    dim3 g3grid((VV + 127) / 128, BB / 64);          // 102 x 8 = 816 blocks
    for (int t = 0; t < SS; ++t) {
        long long off = scores_out ? (long long)t * VV : 0;
        gates_fused_kernel<<<g1grid, 256>>>(t);
        scores_mma_kernel<<<g3grid, 256, SCORES_SMEM>>>(out_b, ord_masks, sc_base, pitch, off,
                                                        order_emb, idx_out, t);
    }
}